// round 4
// baseline (speedup 1.0000x reference)
#include <cuda_runtime.h>

// IF spiking neuron forward (R4):
//   x: [T=8, N=4194304] fp32, thresh: [1] fp32
//   mem = 0.5*thr; per t: m = mem + x[t]; s = (m>=thr); out[t] = s*thr; mem = m - s*thr
//
// R4 = R2 shape (1 float4/thread, 32 regs, ~81% occ — the best measured config)
//      + __ldcs/__stcs streaming hints in isolation (zero-reuse 256MB stream).

#define T_STEPS 8
#define N_NEURONS (256 / T_STEPS * 512 * 16 * 16)   // 4,194,304
#define N4 (N_NEURONS / 4)                           // 1,048,576 float4 per timestep
#define TPB 512

__global__ __launch_bounds__(TPB) void if_forward_kernel(
    const float4* __restrict__ x,
    const float* __restrict__ thresh,
    float4* __restrict__ out)
{
    const int i = blockIdx.x * TPB + threadIdx.x;  // grid exactly covers N4
    const float thr = __ldg(thresh);

    // Front-batch all 8 timestep loads (MLP = 8 x LDG.128 per thread).
    float4 xv[T_STEPS];
#pragma unroll
    for (int t = 0; t < T_STEPS; t++) {
        xv[t] = __ldcs(&x[(size_t)t * N4 + i]);
    }

    float m0 = 0.5f * thr, m1 = m0, m2 = m0, m3 = m0;

#pragma unroll
    for (int t = 0; t < T_STEPS; t++) {
        m0 += xv[t].x;
        m1 += xv[t].y;
        m2 += xv[t].z;
        m3 += xv[t].w;
        float4 sp;
        sp.x = (m0 >= thr) ? thr : 0.0f;
        sp.y = (m1 >= thr) ? thr : 0.0f;
        sp.z = (m2 >= thr) ? thr : 0.0f;
        sp.w = (m3 >= thr) ? thr : 0.0f;
        m0 -= sp.x;
        m1 -= sp.y;
        m2 -= sp.z;
        m3 -= sp.w;
        __stcs(&out[(size_t)t * N4 + i], sp);
    }
}

extern "C" void kernel_launch(void* const* d_in, const int* in_sizes, int n_in,
                              void* d_out, int out_size) {
    const float4* x = (const float4*)d_in[0];
    const float* thresh = (const float*)d_in[1];
    float4* out = (float4*)d_out;

    const int blocks = N4 / TPB;  // 2048, exact
    if_forward_kernel<<<blocks, TPB>>>(x, thresh, out);
}